// round 1
// baseline (speedup 1.0000x reference)
#include <cuda_runtime.h>

#define NJ 55
#define BLOCK 96
#define VPT 2
#define VPB (BLOCK * VPT)   // 192 vertices per block

typedef unsigned long long u64;

__device__ __forceinline__ u64 ffma2(u64 a, u64 b, u64 c) {
    u64 d;
    asm("fma.rn.f32x2 %0, %1, %2, %3;" : "=l"(d) : "l"(a), "l"(b), "l"(c));
    return d;
}

__device__ __forceinline__ u64 pack2(float w) {
    u64 d;
    asm("mov.b64 %0, {%1, %1};" : "=l"(d) : "f"(w));
    return d;
}

__device__ __forceinline__ float lo32(u64 v) { return __uint_as_float((unsigned)(v & 0xffffffffu)); }
__device__ __forceinline__ float hi32(u64 v) { return __uint_as_float((unsigned)(v >> 32)); }

__global__ __launch_bounds__(BLOCK)
void lbs_kernel(const float* __restrict__ points,
                const float* __restrict__ weights,
                const float* __restrict__ se3,
                float* __restrict__ out,
                int N)
{
    // SE3 rows 0..2 of each joint as float4: s_se3[(j*3 + r)*4 + c]
    __shared__ __align__(16) float s_se3[NJ * 3 * 4];
    // staged weights: s_w[v_local * NJ + j], v_local in [0, VPB)
    __shared__ __align__(16) float s_w[VPB * NJ];

    const int t = threadIdx.x;

    // ---- stage SE3 (165 float4 of the 220; only rows 0..2 needed) ----
    {
        const float4* g4 = (const float4*)se3;
        float4* s4 = (float4*)s_se3;
        for (int i = t; i < NJ * 3; i += BLOCK) {
            int j = i / 3;
            int r = i - 3 * j;
            s4[i] = g4[j * 4 + r];
        }
    }
    __syncthreads();

    const int b0 = blockIdx.x * VPB;
    const int warp = t >> 5;
    const int lane = t & 31;

    // ---- per-warp coalesced staging of this warp's weight rows ----
    // warp's vertices: chunk c covers local verts [c*BLOCK + warp*32, +32)
    #pragma unroll
    for (int c = 0; c < VPT; c++) {
        int lv = c * BLOCK + warp * 32;
        long gv = (long)b0 + lv;
        long rv = (long)N - gv;
        if (rv >= 32) {
            // 32*55 floats = 440 float4, base divisible by 4 (192,96,32 all *55 %4==0)
            const float4* src = (const float4*)weights + ((gv * NJ) >> 2);
            float4* dst = (float4*)s_w + ((lv * NJ) >> 2);
            for (int i = lane; i < (32 * NJ) / 4; i += 32) dst[i] = src[i];
        } else if (rv > 0) {
            int nf = (int)rv * NJ;
            for (int i = lane; i < nf; i += 32)
                s_w[lv * NJ + i] = weights[gv * NJ + i];
        }
    }
    __syncwarp();

    // ---- blend: A = sum_j w_j * SE3_j (rows 0..2), packed f32x2 ----
    const int v0 = b0 + t;
    const int v1 = v0 + BLOCK;
    const float* w0 = s_w + t * NJ;
    const float* w1 = s_w + (t + BLOCK) * NJ;

    u64 acc0[6], acc1[6];
    #pragma unroll
    for (int i = 0; i < 6; i++) { acc0[i] = 0ull; acc1[i] = 0ull; }

    #pragma unroll
    for (int j = 0; j < NJ; j++) {
        const ulonglong2* sr = (const ulonglong2*)(s_se3 + j * 12);
        ulonglong2 r0 = sr[0];   // row0: (a00,a01),(a02,a03)
        ulonglong2 r1 = sr[1];
        ulonglong2 r2 = sr[2];

        u64 ww0 = pack2(w0[j]);
        acc0[0] = ffma2(ww0, r0.x, acc0[0]);
        acc0[1] = ffma2(ww0, r0.y, acc0[1]);
        acc0[2] = ffma2(ww0, r1.x, acc0[2]);
        acc0[3] = ffma2(ww0, r1.y, acc0[3]);
        acc0[4] = ffma2(ww0, r2.x, acc0[4]);
        acc0[5] = ffma2(ww0, r2.y, acc0[5]);

        u64 ww1 = pack2(w1[j]);
        acc1[0] = ffma2(ww1, r0.x, acc1[0]);
        acc1[1] = ffma2(ww1, r0.y, acc1[1]);
        acc1[2] = ffma2(ww1, r1.x, acc1[2]);
        acc1[3] = ffma2(ww1, r1.y, acc1[3]);
        acc1[4] = ffma2(ww1, r2.x, acc1[4]);
        acc1[5] = ffma2(ww1, r2.y, acc1[5]);
    }

    // ---- epilogue: out = R p + T ----
    if (v0 < N) {
        float px = points[3 * v0 + 0];
        float py = points[3 * v0 + 1];
        float pz = points[3 * v0 + 2];
        #pragma unroll
        for (int r = 0; r < 3; r++) {
            float a0 = lo32(acc0[2 * r]);
            float a1 = hi32(acc0[2 * r]);
            float a2 = lo32(acc0[2 * r + 1]);
            float a3 = hi32(acc0[2 * r + 1]);
            out[3 * v0 + r] = fmaf(a0, px, fmaf(a1, py, fmaf(a2, pz, a3)));
        }
    }
    if (v1 < N) {
        float px = points[3 * v1 + 0];
        float py = points[3 * v1 + 1];
        float pz = points[3 * v1 + 2];
        #pragma unroll
        for (int r = 0; r < 3; r++) {
            float a0 = lo32(acc1[2 * r]);
            float a1 = hi32(acc1[2 * r]);
            float a2 = lo32(acc1[2 * r + 1]);
            float a3 = hi32(acc1[2 * r + 1]);
            out[3 * v1 + r] = fmaf(a0, px, fmaf(a1, py, fmaf(a2, pz, a3)));
        }
    }
}

extern "C" void kernel_launch(void* const* d_in, const int* in_sizes, int n_in,
                              void* d_out, int out_size)
{
    const int N = out_size / 3;
    const float* points = nullptr;
    const float* weights = nullptr;
    const float* se3 = nullptr;

    // identify inputs by element count (robust to metadata ordering)
    for (int i = 0; i < n_in; i++) {
        long sz = in_sizes[i];
        if (sz == (long)NJ * 16)           se3 = (const float*)d_in[i];
        else if (sz == (long)N * NJ)       weights = (const float*)d_in[i];
        else if (sz == (long)N * 3)        points = (const float*)d_in[i];
    }

    int nb = (N + VPB - 1) / VPB;
    lbs_kernel<<<nb, BLOCK>>>(points, weights, se3, (float*)d_out, N);
}

// round 6
// speedup vs baseline: 1.1878x; 1.1878x over previous
#include <cuda_runtime.h>
#include <cuda_fp16.h>

#define NJ 55
#define BLOCK 128
#define VPT 2
#define VPB (BLOCK * VPT)   // 256 vertices per block
#define MAXBLK 6

typedef unsigned long long u64;

__device__ __forceinline__ u64 ffma2(u64 a, u64 b, u64 c) {
    u64 d;
    asm("fma.rn.f32x2 %0, %1, %2, %3;" : "=l"(d) : "l"(a), "l"(b), "l"(c));
    return d;
}

__device__ __forceinline__ u64 pack2(float w) {
    u64 d;
    asm("mov.b64 %0, {%1, %1};" : "=l"(d) : "f"(w));
    return d;
}

__device__ __forceinline__ float lo32(u64 v) { return __uint_as_float((unsigned)(v & 0xffffffffu)); }
__device__ __forceinline__ float hi32(u64 v) { return __uint_as_float((unsigned)(v >> 32)); }

__global__ __launch_bounds__(BLOCK, MAXBLK)
void lbs_kernel(const float* __restrict__ points,
                const float* __restrict__ weights,
                const float* __restrict__ se3,
                float* __restrict__ out,
                int N)
{
    // SE3 rows 0..2 of each joint as float4: s_se3[(j*3 + r)*4 + c]
    __shared__ __align__(16) float s_se3[NJ * 3 * 4];
    // staged weights in fp16: s_w[v_local * NJ + j], v_local in [0, VPB)
    __shared__ __align__(8) __half s_w[VPB * NJ];

    const int t = threadIdx.x;

    // ---- stage SE3 (rows 0..2 only) ----
    {
        const float4* g4 = (const float4*)se3;
        float4* s4 = (float4*)s_se3;
        for (int i = t; i < NJ * 3; i += BLOCK) {
            int j = i / 3;
            int r = i - 3 * j;
            s4[i] = g4[j * 4 + r];
        }
    }
    __syncthreads();

    const int b0 = blockIdx.x * VPB;
    const int warp = t >> 5;
    const int lane = t & 31;

    // ---- per-warp coalesced staging of this warp's weight rows (fp32->fp16) ----
    // chunk c covers local verts [c*BLOCK + warp*32, +32)
    #pragma unroll
    for (int c = 0; c < VPT; c++) {
        int lv = c * BLOCK + warp * 32;
        long gv = (long)b0 + lv;
        long rv = (long)N - gv;
        if (rv >= 32) {
            // 32*55 = 1760 floats = 440 float4; gv*55 divisible by 4 (gv multiple of 32)
            const float4* src = (const float4*)weights + ((gv * NJ) >> 2);
            __half2* dst = (__half2*)(s_w + lv * NJ);   // 4B aligned (lv*55 even)
            for (int i = lane; i < (32 * NJ) / 4; i += 32) {
                float4 f = src[i];
                dst[2 * i + 0] = __floats2half2_rn(f.x, f.y);
                dst[2 * i + 1] = __floats2half2_rn(f.z, f.w);
            }
        } else if (rv > 0) {
            int nf = (int)rv * NJ;
            for (int i = lane; i < nf; i += 32)
                s_w[lv * NJ + i] = __float2half_rn(weights[gv * NJ + i]);
        }
    }
    __syncwarp();

    // ---- blend: A = sum_j w_j * SE3_j (rows 0..2), packed f32x2 ----
    const int v0 = b0 + t;
    const int v1 = v0 + BLOCK;
    const __half* w0 = s_w + t * NJ;
    const __half* w1 = s_w + (t + BLOCK) * NJ;

    u64 acc0[6], acc1[6];
    #pragma unroll
    for (int i = 0; i < 6; i++) { acc0[i] = 0ull; acc1[i] = 0ull; }

    #pragma unroll
    for (int j = 0; j < NJ; j++) {
        const ulonglong2* sr = (const ulonglong2*)(s_se3 + j * 12);
        ulonglong2 r0 = sr[0];   // row0: (a00,a01),(a02,a03)
        ulonglong2 r1 = sr[1];
        ulonglong2 r2 = sr[2];

        u64 ww0 = pack2(__half2float(w0[j]));
        acc0[0] = ffma2(ww0, r0.x, acc0[0]);
        acc0[1] = ffma2(ww0, r0.y, acc0[1]);
        acc0[2] = ffma2(ww0, r1.x, acc0[2]);
        acc0[3] = ffma2(ww0, r1.y, acc0[3]);
        acc0[4] = ffma2(ww0, r2.x, acc0[4]);
        acc0[5] = ffma2(ww0, r2.y, acc0[5]);

        u64 ww1 = pack2(__half2float(w1[j]));
        acc1[0] = ffma2(ww1, r0.x, acc1[0]);
        acc1[1] = ffma2(ww1, r0.y, acc1[1]);
        acc1[2] = ffma2(ww1, r1.x, acc1[2]);
        acc1[3] = ffma2(ww1, r1.y, acc1[3]);
        acc1[4] = ffma2(ww1, r2.x, acc1[4]);
        acc1[5] = ffma2(ww1, r2.y, acc1[5]);
    }

    // ---- epilogue: out = R p + T ----
    if (v0 < N) {
        float px = points[3 * v0 + 0];
        float py = points[3 * v0 + 1];
        float pz = points[3 * v0 + 2];
        #pragma unroll
        for (int r = 0; r < 3; r++) {
            float a0 = lo32(acc0[2 * r]);
            float a1 = hi32(acc0[2 * r]);
            float a2 = lo32(acc0[2 * r + 1]);
            float a3 = hi32(acc0[2 * r + 1]);
            out[3 * v0 + r] = fmaf(a0, px, fmaf(a1, py, fmaf(a2, pz, a3)));
        }
    }
    if (v1 < N) {
        float px = points[3 * v1 + 0];
        float py = points[3 * v1 + 1];
        float pz = points[3 * v1 + 2];
        #pragma unroll
        for (int r = 0; r < 3; r++) {
            float a0 = lo32(acc1[2 * r]);
            float a1 = hi32(acc1[2 * r]);
            float a2 = lo32(acc1[2 * r + 1]);
            float a3 = hi32(acc1[2 * r + 1]);
            out[3 * v1 + r] = fmaf(a0, px, fmaf(a1, py, fmaf(a2, pz, a3)));
        }
    }
}

extern "C" void kernel_launch(void* const* d_in, const int* in_sizes, int n_in,
                              void* d_out, int out_size)
{
    const int N = out_size / 3;
    const float* points = nullptr;
    const float* weights = nullptr;
    const float* se3 = nullptr;

    for (int i = 0; i < n_in; i++) {
        long sz = in_sizes[i];
        if (sz == (long)NJ * 16)           se3 = (const float*)d_in[i];
        else if (sz == (long)N * NJ)       weights = (const float*)d_in[i];
        else if (sz == (long)N * 3)        points = (const float*)d_in[i];
    }

    int nb = (N + VPB - 1) / VPB;
    lbs_kernel<<<nb, BLOCK>>>(points, weights, se3, (float*)d_out, N);
}

// round 8
// speedup vs baseline: 1.1896x; 1.0016x over previous
#include <cuda_runtime.h>
#include <cuda_fp16.h>
#include <cstdint>

#define NJ      55
#define TILE_M  128
#define KPAD    64
#define BLOCK   128
#define GRID_P  888     // 148 SM x 6 blocks

__device__ __forceinline__ uint32_t smem_u32(const void* p) {
    uint32_t a;
    asm("{ .reg .u64 t; cvta.to.shared.u64 t, %1; cvt.u32.u64 %0, t; }" : "=r"(a) : "l"(p));
    return a;
}

__device__ __forceinline__ void ldsm_x4(uint32_t* r, uint32_t addr) {
    asm volatile("ldmatrix.sync.aligned.m8n8.x4.shared.b16 {%0,%1,%2,%3}, [%4];"
                 : "=r"(r[0]), "=r"(r[1]), "=r"(r[2]), "=r"(r[3]) : "r"(addr));
}

__device__ __forceinline__ void mma16816(float* d, const uint32_t* a, uint32_t b0, uint32_t b1) {
    asm volatile("mma.sync.aligned.m16n8k16.row.col.f32.f16.f16.f32 "
                 "{%0,%1,%2,%3}, {%4,%5,%6,%7}, {%8,%9}, {%0,%1,%2,%3};"
                 : "+f"(d[0]), "+f"(d[1]), "+f"(d[2]), "+f"(d[3])
                 : "r"(a[0]), "r"(a[1]), "r"(a[2]), "r"(a[3]), "r"(b0), "r"(b1));
}

__global__ __launch_bounds__(BLOCK, 6)
void lbs_hmma_kernel(const float* __restrict__ points,
                     const float* __restrict__ weights,
                     const float* __restrict__ se3,
                     float* __restrict__ out,
                     int N, int n_tiles)
{
    // A tile: [128 rows][64 halves], 128B rows, 8-row XOR-16B swizzle
    __shared__ __align__(1024) __half s_A[TILE_M * KPAD];        // 16 KB
    // B: [16 n-rows][64 k], hi and lo parts
    __shared__ __align__(1024) __half s_B[2][16 * KPAD];         // 4 KB
    // per-warp linear staging of 32 weight rows; reused as D-exchange [32][20] f32
    __shared__ __align__(16)   __half s_lin[4][32 * NJ];         // 14.08 KB

    const int tid  = threadIdx.x;
    const int wid  = tid >> 5;
    const int lane = tid & 31;

    const uint32_t a_base  = smem_u32(s_A);
    const uint32_t b0_base = smem_u32(s_B[0]);
    const uint32_t b1_base = smem_u32(s_B[1]);

    // ---- build B (hi/lo split of SE3 rows 0..2 flattened as n = r*4+c), once ----
    for (int idx = tid; idx < 16 * KPAD; idx += BLOCK) {
        int n = idx >> 6;          // 0..15 (flat 3x4 entry; 12..15 -> zero rows)
        int k = idx & 63;          // joint
        float v = (k < NJ && n < 12) ? se3[k * 16 + n] : 0.0f;
        __half hh = __float2half_rn(v);
        __half hl = __float2half_rn(v - __half2float(hh));
        uint32_t off = (uint32_t)(n * 128 + 2 * k);
        off ^= ((off >> 3) & 0x70);
        *(__half*)((char*)s_B[0] + off) = hh;
        *(__half*)((char*)s_B[1] + off) = hl;
    }
    __syncthreads();

    for (int tile = blockIdx.x; tile < n_tiles; tile += gridDim.x) {
        // ---- stage: coalesced LDG -> fp16 linear rows (warp-local) ----
        long gv0 = (long)tile * TILE_M + wid * 32;
        long rem = (long)N - gv0;
        if (rem >= 32) {
            const float4* src = (const float4*)weights + ((gv0 * NJ) >> 2); // gv0%32==0
            __half2* dst = (__half2*)(s_lin[wid]);
            #pragma unroll 4
            for (int i = lane; i < (32 * NJ) / 4; i += 32) {
                float4 f = src[i];
                dst[2 * i + 0] = __floats2half2_rn(f.x, f.y);
                dst[2 * i + 1] = __floats2half2_rn(f.z, f.w);
            }
        } else if (rem > 0) {
            int nf = (int)rem * NJ;
            for (int i = lane; i < nf; i += 32)
                s_lin[wid][i] = __float2half_rn(weights[gv0 * NJ + i]);
        }
        __syncwarp();

        // ---- repack: thread = one row -> swizzled A tile (K zero-padded to 64) ----
        {
            const unsigned short* rp = (const unsigned short*)(s_lin[wid] + lane * NJ);
            const uint32_t rowbase = a_base + (uint32_t)(wid * 32 + lane) * 128;
            const uint32_t xr = (uint32_t)(lane & 7) << 4;  // (row%8)*16
            #pragma unroll
            for (int b = 0; b < 8; b++) {
                uint32_t h[4];
                #pragma unroll
                for (int q = 0; q < 4; q++) {
                    int idx = 4 * b + q;                     // half-pair index
                    uint32_t lo = (2 * idx     < NJ) ? rp[2 * idx]     : 0u;
                    uint32_t hi = (2 * idx + 1 < NJ) ? rp[2 * idx + 1] : 0u;
                    h[q] = lo | (hi << 16);
                }
                uint32_t ad = rowbase + (((uint32_t)(b * 16)) ^ xr);
                asm volatile("st.shared.v4.b32 [%0], {%1,%2,%3,%4};"
                             :: "r"(ad), "r"(h[0]), "r"(h[1]), "r"(h[2]), "r"(h[3]) : "memory");
            }
        }
        __syncwarp();

        // ---- MMA: D[32x16] = A_warp[32x64] * (Bh + Bl)^T ----
        float d[4][4];   // [mt*2+nt][4]
        #pragma unroll
        for (int i = 0; i < 4; i++)
            #pragma unroll
            for (int q = 0; q < 4; q++) d[i][q] = 0.0f;

        #pragma unroll
        for (int chunk = 0; chunk < 4; chunk++) {
            // A fragments, two 16x16 m-tiles
            uint32_t a0[4], a1[4];
            {
                int rowa = wid * 32 + (lane & 15);
                uint32_t c = (uint32_t)(chunk * 32) + (((uint32_t)lane >> 4) << 4);
                uint32_t ad = a_base + (uint32_t)rowa * 128 + (c ^ ((uint32_t)(rowa & 7) << 4));
                ldsm_x4(a0, ad);
                ldsm_x4(a1, ad + 16 * 128);   // +16 rows: (row&7) unchanged, swizzle identical
            }
            // B fragments (x4 covers both n-tiles for this k16 chunk)
            uint32_t bh[4], bl[4];
            {
                int nrow = (lane & 7) + (((lane >> 4) & 1) << 3);
                uint32_t c = (uint32_t)(chunk * 32) + (((uint32_t)(lane >> 3) & 1) << 4);
                uint32_t boff = (uint32_t)nrow * 128 + (c ^ ((uint32_t)(nrow & 7) << 4));
                ldsm_x4(bh, b0_base + boff);
                ldsm_x4(bl, b1_base + boff);
            }
            mma16816(d[0], a0, bh[0], bh[1]);
            mma16816(d[1], a0, bh[2], bh[3]);
            mma16816(d[2], a1, bh[0], bh[1]);
            mma16816(d[3], a1, bh[2], bh[3]);
            mma16816(d[0], a0, bl[0], bl[1]);
            mma16816(d[1], a0, bl[2], bl[3]);
            mma16816(d[2], a1, bl[0], bl[1]);
            mma16816(d[3], a1, bl[2], bl[3]);
        }

        // ---- D exchange through smem (reuse s_lin[wid] as [32][20] f32) ----
        float* dex = (float*)(s_lin[wid]);
        {
            int r0 = lane >> 2;
            int cq = 2 * (lane & 3);
            #pragma unroll
            for (int mt = 0; mt < 2; mt++) {
                #pragma unroll
                for (int nt = 0; nt < 2; nt++) {
                    float* dd = d[mt * 2 + nt];
                    int rr = mt * 16 + r0;
                    int cc = nt * 8 + cq;
                    *(float2*)(dex + rr * 20 + cc)       = make_float2(dd[0], dd[1]);
                    *(float2*)(dex + (rr + 8) * 20 + cc) = make_float2(dd[2], dd[3]);
                }
            }
        }
        __syncwarp();

        // ---- epilogue: out = A3x4 * [p;1] ----
        long v = gv0 + lane;
        if (v < N) {
            float4 q0 = *(const float4*)(dex + lane * 20 + 0);   // A row0: a00 a01 a02 a03
            float4 q1 = *(const float4*)(dex + lane * 20 + 4);   // A row1
            float4 q2 = *(const float4*)(dex + lane * 20 + 8);   // A row2
            float px = points[3 * v + 0];
            float py = points[3 * v + 1];
            float pz = points[3 * v + 2];
            out[3 * v + 0] = fmaf(q0.x, px, fmaf(q0.y, py, fmaf(q0.z, pz, q0.w)));
            out[3 * v + 1] = fmaf(q1.x, px, fmaf(q1.y, py, fmaf(q1.z, pz, q1.w)));
            out[3 * v + 2] = fmaf(q2.x, px, fmaf(q2.y, py, fmaf(q2.z, pz, q2.w)));
        }
        __syncwarp();   // D reads done before next iteration's stage overwrites s_lin
    }
}

extern "C" void kernel_launch(void* const* d_in, const int* in_sizes, int n_in,
                              void* d_out, int out_size)
{
    const int N = out_size / 3;
    const float* points = nullptr;
    const float* weights = nullptr;
    const float* se3 = nullptr;

    for (int i = 0; i < n_in; i++) {
        long sz = in_sizes[i];
        if (sz == (long)NJ * 16)      se3 = (const float*)d_in[i];
        else if (sz == (long)N * NJ)  weights = (const float*)d_in[i];
        else if (sz == (long)N * 3)   points = (const float*)d_in[i];
    }

    int n_tiles = (N + TILE_M - 1) / TILE_M;
    int grid = n_tiles < GRID_P ? n_tiles : GRID_P;
    lbs_hmma_kernel<<<grid, BLOCK>>>(points, weights, se3, (float*)d_out, N, n_tiles);
}

// round 9
// speedup vs baseline: 1.6895x; 1.4202x over previous
#include <cuda_runtime.h>
#include <cuda_fp16.h>
#include <cstdint>

#define NJ      55
#define TILE_M  128
#define KPAD    64
#define BLOCK   128
#define GRID_P  592     // 148 SM x 4 blocks

__device__ __forceinline__ uint32_t smem_u32(const void* p) {
    uint32_t a;
    asm("{ .reg .u64 t; cvta.to.shared.u64 t, %1; cvt.u32.u64 %0, t; }" : "=r"(a) : "l"(p));
    return a;
}

__device__ __forceinline__ void ldsm_x4(uint32_t* r, uint32_t addr) {
    asm volatile("ldmatrix.sync.aligned.m8n8.x4.shared.b16 {%0,%1,%2,%3}, [%4];"
                 : "=r"(r[0]), "=r"(r[1]), "=r"(r[2]), "=r"(r[3]) : "r"(addr));
}

__device__ __forceinline__ void mma16816(float* d, const uint32_t* a, uint32_t b0, uint32_t b1) {
    asm volatile("mma.sync.aligned.m16n8k16.row.col.f32.f16.f16.f32 "
                 "{%0,%1,%2,%3}, {%4,%5,%6,%7}, {%8,%9}, {%0,%1,%2,%3};"
                 : "+f"(d[0]), "+f"(d[1]), "+f"(d[2]), "+f"(d[3])
                 : "r"(a[0]), "r"(a[1]), "r"(a[2]), "r"(a[3]), "r"(b0), "r"(b1));
}

// byte-offset swizzle within a 128B row: XOR 16B-unit index with (row%8)
__device__ __forceinline__ uint32_t swb(uint32_t b, int r) {
    return (b & 15u) | ((((b >> 4) ^ (uint32_t)(r & 7)) & 7u) << 4);
}

// async-stage one warp's 32 weight rows (raw fp32) into its slab
__device__ __forceinline__ void stage_copy(const float* __restrict__ weights,
                                           float* dst, long gv0, long N, int lane)
{
    long rem = N - gv0;
    if (rem >= 32) {
        const float4* src = (const float4*)(weights + gv0 * NJ);  // gv0%32==0 -> 16B aligned
        #pragma unroll 2
        for (int i = lane; i < (32 * NJ) / 4; i += 32) {
            uint32_t da = smem_u32((const float4*)dst + i);
            asm volatile("cp.async.cg.shared.global [%0], [%1], 16;"
                         :: "r"(da), "l"(src + i) : "memory");
        }
    } else if (rem > 0) {
        int nf  = (int)rem * NJ;
        int nch = nf >> 2;
        const float4* src = (const float4*)(weights + gv0 * NJ);
        for (int i = lane; i < nch; i += 32) {
            uint32_t da = smem_u32((const float4*)dst + i);
            asm volatile("cp.async.cg.shared.global [%0], [%1], 16;"
                         :: "r"(da), "l"(src + i) : "memory");
        }
        for (int i = 4 * nch + lane; i < nf; i += 32)
            dst[i] = weights[gv0 * NJ + i];
    }
    asm volatile("cp.async.commit_group;" ::: "memory");
}

__global__ __launch_bounds__(BLOCK, 4)
void lbs_hmma_kernel(const float* __restrict__ points,
                     const float* __restrict__ weights,
                     const float* __restrict__ se3,
                     float* __restrict__ out,
                     int N, int n_tiles)
{
    // A tile: [128 rows][64 halves], 128B rows, 8-row XOR-16B swizzle.
    // After MMA, each warp's 4KB A region is reused as its D-exchange buffer.
    __shared__ __align__(1024) __half s_A[TILE_M * KPAD];     // 16 KB
    __shared__ __align__(1024) __half s_B[2][16 * KPAD];      // 4 KB (hi/lo SE3)
    __shared__ __align__(16)   float  s_lin[4][32 * NJ];      // 28.16 KB fp32 slabs

    const int tid  = threadIdx.x;
    const int wid  = tid >> 5;
    const int lane = tid & 31;

    const uint32_t a_base  = smem_u32(s_A);
    const uint32_t b0_base = smem_u32(s_B[0]);
    const uint32_t b1_base = smem_u32(s_B[1]);

    // ---- build B (hi/lo split of SE3 rows 0..2 flattened as n = r*4+c), once ----
    for (int idx = tid; idx < 16 * KPAD; idx += BLOCK) {
        int n = idx >> 6;
        int k = idx & 63;
        float v = (k < NJ && n < 12) ? se3[k * 16 + n] : 0.0f;
        __half hh = __float2half_rn(v);
        __half hl = __float2half_rn(v - __half2float(hh));
        uint32_t off = (uint32_t)(n * 128 + 2 * k);
        off ^= ((off >> 3) & 0x70);
        *(__half*)((char*)s_B[0] + off) = hh;
        *(__half*)((char*)s_B[1] + off) = hl;
    }
    __syncthreads();

    // ---- prologue: prefetch first tile's slab ----
    int tile = blockIdx.x;
    if (tile < n_tiles)
        stage_copy(weights, s_lin[wid], (long)tile * TILE_M + wid * 32, N, lane);

    for (; tile < n_tiles; tile += gridDim.x) {
        const long gv0 = (long)tile * TILE_M + wid * 32;

        // ---- wait this tile's slab, pull own row into packed fp16 regs ----
        asm volatile("cp.async.wait_group 0;" ::: "memory");
        __syncwarp();

        uint32_t h[28];
        {
            const float* rp = s_lin[wid] + lane * NJ;
            #pragma unroll
            for (int q = 0; q < 27; q++) {
                __half2 p = __floats2half2_rn(rp[2 * q], rp[2 * q + 1]);
                h[q] = *(uint32_t*)&p;
            }
            __half2 p = __floats2half2_rn(rp[54], 0.0f);
            h[27] = *(uint32_t*)&p;
        }
        __syncwarp();

        // ---- issue prefetch for next tile (slab now free) ----
        {
            long nt = (long)tile + gridDim.x;
            if (nt < n_tiles)
                stage_copy(weights, s_lin[wid], nt * TILE_M + wid * 32, N, lane);
        }

        // ---- repack regs -> swizzled A tile (K zero-padded to 64) ----
        {
            const uint32_t rowbase = a_base + (uint32_t)(wid * 32 + lane) * 128;
            const uint32_t xr = (uint32_t)(lane & 7) << 4;
            #pragma unroll
            for (int b = 0; b < 8; b++) {
                uint32_t h0 = (4 * b + 0 < 28) ? h[4 * b + 0] : 0u;
                uint32_t h1 = (4 * b + 1 < 28) ? h[4 * b + 1] : 0u;
                uint32_t h2 = (4 * b + 2 < 28) ? h[4 * b + 2] : 0u;
                uint32_t h3 = (4 * b + 3 < 28) ? h[4 * b + 3] : 0u;
                uint32_t ad = rowbase + (((uint32_t)(b * 16)) ^ xr);
                asm volatile("st.shared.v4.b32 [%0], {%1,%2,%3,%4};"
                             :: "r"(ad), "r"(h0), "r"(h1), "r"(h2), "r"(h3) : "memory");
            }
        }
        __syncwarp();

        // ---- MMA: D[32x16] = A_warp[32x64] * (Bh + Bl)^T ----
        float d[4][4];
        #pragma unroll
        for (int i = 0; i < 4; i++)
            #pragma unroll
            for (int q = 0; q < 4; q++) d[i][q] = 0.0f;

        #pragma unroll
        for (int chunk = 0; chunk < 4; chunk++) {
            uint32_t a0[4], a1[4];
            {
                int rowa = wid * 32 + (lane & 15);
                uint32_t c = (uint32_t)(chunk * 32) + (((uint32_t)lane >> 4) << 4);
                uint32_t ad = a_base + (uint32_t)rowa * 128 + (c ^ ((uint32_t)(rowa & 7) << 4));
                ldsm_x4(a0, ad);
                ldsm_x4(a1, ad + 16 * 128);
            }
            uint32_t bh[4], bl[4];
            {
                int nrow = (lane & 7) + (((lane >> 4) & 1) << 3);
                uint32_t c = (uint32_t)(chunk * 32) + (((uint32_t)(lane >> 3) & 1) << 4);
                uint32_t boff = (uint32_t)nrow * 128 + (c ^ ((uint32_t)(nrow & 7) << 4));
                ldsm_x4(bh, b0_base + boff);
                ldsm_x4(bl, b1_base + boff);
            }
            mma16816(d[0], a0, bh[0], bh[1]);
            mma16816(d[1], a0, bh[2], bh[3]);
            mma16816(d[2], a1, bh[0], bh[1]);
            mma16816(d[3], a1, bh[2], bh[3]);
            mma16816(d[0], a0, bl[0], bl[1]);
            mma16816(d[1], a0, bl[2], bl[3]);
            mma16816(d[2], a1, bl[0], bl[1]);
            mma16816(d[3], a1, bl[2], bl[3]);
        }

        // ---- D exchange through the (now dead) A region, swizzled ----
        {
            char* awarp = (char*)s_A + (wid * 32) * 128;
            int r0 = lane >> 2;
            int cq = 2 * (lane & 3);
            #pragma unroll
            for (int mt = 0; mt < 2; mt++) {
                #pragma unroll
                for (int nt = 0; nt < 2; nt++) {
                    float* dd = d[mt * 2 + nt];
                    int rr = mt * 16 + r0;
                    uint32_t cb = (uint32_t)(nt * 8 + cq) * 4;   // byte col, %16 in {0,8}
                    *(float2*)(awarp + rr * 128 + swb(cb, rr))
                        = make_float2(dd[0], dd[1]);
                    *(float2*)(awarp + (rr + 8) * 128 + swb(cb, rr + 8))
                        = make_float2(dd[2], dd[3]);
                }
            }
        }
        __syncwarp();

        // ---- epilogue: out = A3x4 * [p;1] ----
        long v = gv0 + lane;
        if (v < N) {
            char* awarp = (char*)s_A + (wid * 32) * 128;
            float4 q0 = *(float4*)(awarp + lane * 128 + swb(0u,  lane));
            float4 q1 = *(float4*)(awarp + lane * 128 + swb(16u, lane));
            float4 q2 = *(float4*)(awarp + lane * 128 + swb(32u, lane));
            float px = points[3 * v + 0];
            float py = points[3 * v + 1];
            float pz = points[3 * v + 2];
            out[3 * v + 0] = fmaf(q0.x, px, fmaf(q0.y, py, fmaf(q0.z, pz, q0.w)));
            out[3 * v + 1] = fmaf(q1.x, px, fmaf(q1.y, py, fmaf(q1.z, pz, q1.w)));
            out[3 * v + 2] = fmaf(q2.x, px, fmaf(q2.y, py, fmaf(q2.z, pz, q2.w)));
        }
        __syncwarp();   // exchange reads done before next iter's repack overwrites A
    }
}

extern "C" void kernel_launch(void* const* d_in, const int* in_sizes, int n_in,
                              void* d_out, int out_size)
{
    const int N = out_size / 3;
    const float* points = nullptr;
    const float* weights = nullptr;
    const float* se3 = nullptr;

    for (int i = 0; i < n_in; i++) {
        long sz = in_sizes[i];
        if (sz == (long)NJ * 16)      se3 = (const float*)d_in[i];
        else if (sz == (long)N * NJ)  weights = (const float*)d_in[i];
        else if (sz == (long)N * 3)   points = (const float*)d_in[i];
    }

    int n_tiles = (N + TILE_M - 1) / TILE_M;
    int grid = n_tiles < GRID_P ? n_tiles : GRID_P;
    lbs_hmma_kernel<<<grid, BLOCK>>>(points, weights, se3, (float*)d_out, N, n_tiles);
}